// round 4
// baseline (speedup 1.0000x reference)
#include <cuda_runtime.h>
#include <cstdint>

// Type-2 NUFFT, separable twiddles, packed-f32x2 mainloop.
//   y[b,c,m] = sum_iy ey[m,iy] * ( sum_ix ex[m,ix] * x[b,c,iy,ix] )
// Lane L owns image rows {2L, 2L+1}; the row pair rides in one f32x2 register,
// so every complex MAC is one fma.rn.f32x2 (full-rate fp32 on sm_103a).

#define NB 16
#define NC 4
#define NH 64
#define NW 64
#define NM 2048

#define TS 4                       // samples per warp
#define NWARPS 16
#define NTHREADS (NWARPS * 32)     // 512
#define SPC (NWARPS * TS)          // 64 samples per CTA
#define BLKS_PER_B (NM / SPC)      // 32

// smem (floats): image 64*4*128 = 32768, tabx 64*64*4 = 16384, taby 64*64*2 = 8192
#define XS_FLOATS   (NW * NC * 128)
#define TABX_FLOATS (SPC * NW * 4)
#define TABY_FLOATS (SPC * NH * 2)
#define SMEM_BYTES  ((XS_FLOATS + TABX_FLOATS + TABY_FLOATS) * 4)   // 229376 B

__device__ __forceinline__ void fma2(unsigned long long& d,
                                     unsigned long long a,
                                     unsigned long long b)
{
    asm("fma.rn.f32x2 %0, %1, %2, %0;" : "+l"(d) : "l"(a), "l"(b));
}

__device__ __forceinline__ float lo32(unsigned long long v)
{
    return __uint_as_float((unsigned)(v & 0xffffffffu));
}
__device__ __forceinline__ float hi32(unsigned long long v)
{
    return __uint_as_float((unsigned)(v >> 32));
}

__global__ void __launch_bounds__(NTHREADS, 1)
nufft2_kernel(const float* __restrict__ xre, const float* __restrict__ xim,
              const float* __restrict__ traj, float* __restrict__ out)
{
    extern __shared__ float sm[];
    float* xs   = sm;                              // [ix][c][{re_e,re_o,im_e,im_o} x 32 pairs]
    float* tabx = sm + XS_FLOATS;                  // [s][ix][{cs,cs,sn,sn}]
    float* taby = sm + XS_FLOATS + TABX_FLOATS;    // [s][iy][{cs,sn}]

    const int b    = blockIdx.x / BLKS_PER_B;
    const int mblk = blockIdx.x % BLKS_PER_B;
    const int m0   = mblk * SPC;
    const int tid  = threadIdx.x;

    // ---- stage x[b] into packed-pair layout ----
    // idx -> (c, ix, iy) with iy fastest so smem writes are near-conflict-free;
    // global reads are strided but L2-resident (image reused by 32 CTAs).
    const float* xrb = xre + (size_t)b * (NC * NH * NW);
    const float* xib = xim + (size_t)b * (NC * NH * NW);
    #pragma unroll 4
    for (int idx = tid; idx < NC * NH * NW; idx += NTHREADS) {
        int iy = idx & 63;
        int ix = (idx >> 6) & 63;
        int c  = idx >> 12;
        int g  = c * 4096 + iy * 64 + ix;
        float vr = __ldg(xrb + g);
        float vi = __ldg(xib + g);
        int d = (ix * 4 + c) * 128 + ((iy >> 1) << 2) + (iy & 1);
        xs[d]     = vr;   // re plane
        xs[d + 2] = vi;   // im plane
    }

    // ---- twiddle tables ----
    // ex (x-axis, pairs with gx) uses traj[...,1]; ey uses traj[...,0]
    #pragma unroll 1
    for (int e = tid; e < SPC * NW; e += NTHREADS) {
        int s  = e >> 6;
        int ix = e & 63;
        float t1 = traj[((size_t)b * NM + m0 + s) * 2 + 1];
        float ph = -t1 * (float)(ix - 32);
        ph -= 6.283185307179586f * rintf(ph * 0.15915494309189535f);
        float sn, cs;
        __sincosf(ph, &sn, &cs);
        float* d = tabx + e * 4;
        d[0] = cs; d[1] = cs; d[2] = sn; d[3] = sn;
    }
    #pragma unroll 1
    for (int e = tid; e < SPC * NH; e += NTHREADS) {
        int s  = e >> 6;
        int iy = e & 63;
        float t0 = traj[((size_t)b * NM + m0 + s) * 2 + 0];
        float ph = -t0 * (float)(iy - 32);
        ph -= 6.283185307179586f * rintf(ph * 0.15915494309189535f);
        float sn, cs;
        __sincosf(ph, &sn, &cs);
        taby[e * 2 + 0] = cs;
        taby[e * 2 + 1] = sn;
    }
    __syncthreads();

    const int warp = tid >> 5;
    const int lane = tid & 31;

    // lane's float4 slot inside each (ix,c) 128-float block, as ulonglong2
    const ulonglong2* xbase =
        reinterpret_cast<const ulonglong2*>(xs) + lane;   // +1 = 16 bytes
    const unsigned long long* tx0 =
        reinterpret_cast<const unsigned long long*>(tabx) + (size_t)(warp * TS) * 128;

    unsigned long long aR[TS][NC], aI[TS][NC];
    #pragma unroll
    for (int t = 0; t < TS; ++t)
        #pragma unroll
        for (int c = 0; c < NC; ++c) { aR[t][c] = 0ull; aI[t][c] = 0ull; }

    // ---- stage 1: packed complex MACs over ix ----
    #pragma unroll 4
    for (int ix = 0; ix < NW; ++ix) {
        ulonglong2 xv[NC];
        #pragma unroll
        for (int c = 0; c < NC; ++c)
            xv[c] = xbase[(ix * 4 + c) * 32];   // .x = {re_e,re_o}, .y = {im_e,im_o}

        #pragma unroll
        for (int t = 0; t < TS; ++t) {
            unsigned long long cc = tx0[t * 128 + 2 * ix];
            unsigned long long ss = tx0[t * 128 + 2 * ix + 1];
            unsigned long long ns = ss ^ 0x8000000080000000ull;   // {-sn,-sn}
            #pragma unroll
            for (int c = 0; c < NC; ++c) {
                fma2(aR[t][c], cc, xv[c].x);   // += cs*xr
                fma2(aR[t][c], ns, xv[c].y);   // += -sn*xi
                fma2(aI[t][c], cc, xv[c].y);   // += cs*xi
                fma2(aI[t][c], ss, xv[c].x);   // += sn*xr
            }
        }
    }

    // ---- stage 2: y = sum_iy ey[iy] (*) s[iy]; rows {2L, 2L+1} per lane ----
    float zr[TS][NC], zi[TS][NC];
    #pragma unroll
    for (int t = 0; t < TS; ++t) {
        float4 ey = *reinterpret_cast<const float4*>(
            taby + (size_t)(warp * TS + t) * 128 + lane * 4);
        // ey = {cs(2L), sn(2L), cs(2L+1), sn(2L+1)}
        #pragma unroll
        for (int c = 0; c < NC; ++c) {
            float s0r = lo32(aR[t][c]), s1r = hi32(aR[t][c]);
            float s0i = lo32(aI[t][c]), s1i = hi32(aI[t][c]);
            float vr = ey.x * s0r - ey.y * s0i + ey.z * s1r - ey.w * s1i;
            float vi = ey.x * s0i + ey.y * s0r + ey.z * s1i + ey.w * s1r;
            #pragma unroll
            for (int off = 16; off > 0; off >>= 1) {
                vr += __shfl_xor_sync(0xffffffffu, vr, off);
                vi += __shfl_xor_sync(0xffffffffu, vi, off);
            }
            zr[t][c] = vr;
            zi[t][c] = vi;
        }
    }

    if (lane == 0) {
        #pragma unroll
        for (int t = 0; t < TS; ++t) {
            int m = m0 + warp * TS + t;
            #pragma unroll
            for (int c = 0; c < NC; ++c) {
                float2* o = (float2*)(out + (((size_t)b * NC + c) * NM + m) * 2);
                *o = make_float2(zr[t][c], zi[t][c]);
            }
        }
    }
}

extern "C" void kernel_launch(void* const* d_in, const int* in_sizes, int n_in,
                              void* d_out, int out_size)
{
    const float* xre  = (const float*)d_in[0];   // [B,C,H,W] f32
    const float* xim  = (const float*)d_in[1];   // [B,C,H,W] f32
    const float* traj = (const float*)d_in[2];   // [B,M,2]   f32
    float* out        = (float*)d_out;           // [B,C,M,2] f32

    cudaFuncSetAttribute(nufft2_kernel,
                         cudaFuncAttributeMaxDynamicSharedMemorySize, SMEM_BYTES);
    nufft2_kernel<<<NB * BLKS_PER_B, NTHREADS, SMEM_BYTES>>>(xre, xim, traj, out);
}

// round 7
// speedup vs baseline: 1.7554x; 1.7554x over previous
#include <cuda_runtime.h>
#include <cstdint>

// Type-2 NUFFT, separable:
//   stage 1 (tensor, mma.sync tf32): S[m, n=(iy*4+c)] = sum_ix E[m,ix] * X[n,ix]
//   stage 2 (FFMA, in-register):     y[b,c,m] = sum_iy ey[m,iy] (*) S[m,iy,c]
// One CTA per (frame, 64-sample tile): 16*32 = 512 CTAs, 256 threads.
// Dr = Er*Xr + (-Ei)*Xi ; Di = Er*Xi + Ei*Xr   (4 real GEMMs, M=64 N=256 K=64)

#define NBATCH 16
#define NC 4
#define NH 64
#define NW 64
#define NM 2048

#define MT 64                    // samples per CTA
#define MTILES (NM / MT)         // 32
#define NGEMM 256                // n = iy*4 + c
#define KDIM 64                  // k = ix
#define NTHREADS 256

#define ESTRIDE 68               // floats per E row  (bank: 4m+k distinct)
#define XSTRIDE 264              // floats per X k-row (bank: 8k+n distinct)

#define OFF_ER   0
#define OFF_EI   (OFF_ER  + MT * ESTRIDE * 4)          // 17408
#define OFF_EIN  (OFF_EI  + MT * ESTRIDE * 4)          // 34816
#define OFF_XR   (OFF_EIN + MT * ESTRIDE * 4)          // 52224
#define OFF_XI   (OFF_XR  + KDIM * XSTRIDE * 4)        // 119808
#define OFF_PART (OFF_XI  + KDIM * XSTRIDE * 4)        // 187392
#define SMEM_TOTAL (OFF_PART + 4 * MT * NC * 2 * 4)    // 195584 B

static __device__ __forceinline__ uint32_t f2tf32(float f) {
    uint32_t u;
    asm("cvt.rna.tf32.f32 %0, %1;" : "=r"(u) : "f"(f));
    return u;
}

static __device__ __forceinline__ float2 twiddle(float t, int i) {
    float ph = -t * (float)(i - 32);
    ph -= 6.283185307179586f * rintf(ph * 0.15915494309189535f);
    float s, c;
    __sincosf(ph, &s, &c);
    return make_float2(c, s);
}

static __device__ __forceinline__ void mma8(float* d, const uint32_t* a, const uint32_t* b) {
    asm volatile(
        "mma.sync.aligned.m16n8k8.row.col.f32.tf32.tf32.f32 "
        "{%0,%1,%2,%3}, {%4,%5,%6,%7}, {%8,%9}, {%0,%1,%2,%3};"
        : "+f"(d[0]), "+f"(d[1]), "+f"(d[2]), "+f"(d[3])
        : "r"(a[0]), "r"(a[1]), "r"(a[2]), "r"(a[3]), "r"(b[0]), "r"(b[1]));
}

__global__ void __launch_bounds__(NTHREADS, 1)
nufft2_mma_kernel(const float* __restrict__ xre, const float* __restrict__ xim,
                  const float* __restrict__ traj, float* __restrict__ out)
{
    extern __shared__ char smc[];
    uint32_t* ER  = (uint32_t*)(smc + OFF_ER);
    uint32_t* EI  = (uint32_t*)(smc + OFF_EI);
    uint32_t* EIN = (uint32_t*)(smc + OFF_EIN);
    uint32_t* XR  = (uint32_t*)(smc + OFF_XR);
    uint32_t* XI  = (uint32_t*)(smc + OFF_XI);
    float*    PART = (float*)(smc + OFF_PART);   // [qt=4][m=64][c=4][re/im]

    const int b     = blockIdx.x >> 5;
    const int mtile = blockIdx.x & 31;
    const int m0    = mtile * MT;
    const int tid   = threadIdx.x;
    const int wid   = tid >> 5;
    const int lane  = tid & 31;

    // ---- stage E: Er/Ei/-Ei[m][k], tf32; ph = -traj[...,1]*(k-32) ----
    #pragma unroll 2
    for (int e = tid; e < MT * KDIM; e += NTHREADS) {
        int ml = e >> 6, k = e & 63;
        float t1 = __ldg(traj + ((size_t)b * NM + m0 + ml) * 2 + 1);
        float2 w = twiddle(t1, k);
        int d = ml * ESTRIDE + k;
        ER[d]  = f2tf32(w.x);
        EI[d]  = f2tf32(w.y);
        EIN[d] = f2tf32(-w.y);
    }

    // ---- stage X: Xr/Xi[k][n], n = iy*4+c, tf32 (STS conflict-free: n fastest) ----
    const float* xrb = xre + (size_t)b * (NC * NH * NW);
    const float* xib = xim + (size_t)b * (NC * NH * NW);
    #pragma unroll 4
    for (int idx = tid; idx < KDIM * NGEMM; idx += NTHREADS) {
        int n = idx & 255, k = idx >> 8;
        int g = (n & 3) * 4096 + (n >> 2) * 64 + k;
        int d = k * XSTRIDE + n;
        XR[d] = f2tf32(__ldg(xrb + g));
        XI[d] = f2tf32(__ldg(xib + g));
    }
    __syncthreads();

    // ---- mainloop: warp = 2 m16-blocks (mb0 = 2*(wid&1)) x 8 n8-blocks (qt = wid>>1) ----
    const int mb0 = (wid & 1) * 2;
    const int qt  = wid >> 1;
    const int g   = lane >> 2;       // groupID
    const int q   = lane & 3;        // threadID-in-group

    float dr[2][8][4], di[2][8][4];
    #pragma unroll
    for (int mm = 0; mm < 2; ++mm)
        #pragma unroll
        for (int nb = 0; nb < 8; ++nb)
            #pragma unroll
            for (int r = 0; r < 4; ++r) { dr[mm][nb][r] = 0.f; di[mm][nb][r] = 0.f; }

    #pragma unroll 1
    for (int ks = 0; ks < 8; ++ks) {
        const int k0 = ks * 8 + q;
        uint32_t aR[2][4], aI[2][4], aN[2][4];
        #pragma unroll
        for (int mm = 0; mm < 2; ++mm) {
            int r0 = ((mb0 + mm) * 16 + g) * ESTRIDE;
            int r1 = r0 + 8 * ESTRIDE;
            aR[mm][0] = ER[r0 + k0];  aR[mm][1] = ER[r1 + k0];
            aR[mm][2] = ER[r0 + k0 + 4]; aR[mm][3] = ER[r1 + k0 + 4];
            aI[mm][0] = EI[r0 + k0];  aI[mm][1] = EI[r1 + k0];
            aI[mm][2] = EI[r0 + k0 + 4]; aI[mm][3] = EI[r1 + k0 + 4];
            aN[mm][0] = EIN[r0 + k0]; aN[mm][1] = EIN[r1 + k0];
            aN[mm][2] = EIN[r0 + k0 + 4]; aN[mm][3] = EIN[r1 + k0 + 4];
        }
        #pragma unroll
        for (int nb = 0; nb < 8; ++nb) {
            int ncol = qt * 64 + nb * 8 + g;
            uint32_t bR[2], bI[2];
            bR[0] = XR[k0 * XSTRIDE + ncol];
            bR[1] = XR[(k0 + 4) * XSTRIDE + ncol];
            bI[0] = XI[k0 * XSTRIDE + ncol];
            bI[1] = XI[(k0 + 4) * XSTRIDE + ncol];
            #pragma unroll
            for (int mm = 0; mm < 2; ++mm) {
                mma8(dr[mm][nb], aR[mm], bR);
                mma8(dr[mm][nb], aN[mm], bI);
                mma8(di[mm][nb], aR[mm], bI);
                mma8(di[mm][nb], aI[mm], bR);
            }
        }
    }

    // ---- epilogue: ey twiddle in-register, reduce iy ----
    // d-frag: rows {g, g+8} (regs {0,1},{2,3}), cols n = qt*64+nb*8+2q+{0,1}
    //   -> iy = qt*16 + nb*2 + (q>>1), c = (q&1)*2 + {0,1}
    const int cb = (q & 1) * 2;
    #pragma unroll
    for (int mm = 0; mm < 2; ++mm) {
        #pragma unroll
        for (int rr = 0; rr < 2; ++rr) {
            int rowl = (mb0 + mm) * 16 + g + rr * 8;
            float t0 = __ldg(traj + ((size_t)b * NM + m0 + rowl) * 2 + 0);
            float aR0 = 0.f, aI0 = 0.f, aR1 = 0.f, aI1 = 0.f;
            #pragma unroll
            for (int nb = 0; nb < 8; ++nb) {
                float2 ey = twiddle(t0, qt * 16 + nb * 2 + (q >> 1));
                float sr0 = dr[mm][nb][rr * 2 + 0], si0 = di[mm][nb][rr * 2 + 0];
                float sr1 = dr[mm][nb][rr * 2 + 1], si1 = di[mm][nb][rr * 2 + 1];
                aR0 = fmaf(ey.x, sr0, fmaf(-ey.y, si0, aR0));
                aI0 = fmaf(ey.x, si0, fmaf( ey.y, sr0, aI0));
                aR1 = fmaf(ey.x, sr1, fmaf(-ey.y, si1, aR1));
                aI1 = fmaf(ey.x, si1, fmaf( ey.y, sr1, aI1));
            }
            // partner lane (q ^ 2) holds the other iy parity, same c pair
            aR0 += __shfl_xor_sync(0xffffffffu, aR0, 2);
            aI0 += __shfl_xor_sync(0xffffffffu, aI0, 2);
            aR1 += __shfl_xor_sync(0xffffffffu, aR1, 2);
            aI1 += __shfl_xor_sync(0xffffffffu, aI1, 2);
            if (q < 2) {
                float* p = PART + ((qt * MT + rowl) * NC + cb) * 2;
                p[0] = aR0; p[1] = aI0; p[2] = aR1; p[3] = aI1;
            }
        }
    }
    __syncthreads();

    // ---- combine 4 n-quarters, write out ----
    {
        int mlocal = tid >> 2, c = tid & 3;
        float vr = 0.f, vi = 0.f;
        #pragma unroll
        for (int qq = 0; qq < 4; ++qq) {
            const float* p = PART + ((qq * MT + mlocal) * NC + c) * 2;
            vr += p[0]; vi += p[1];
        }
        *(float2*)(out + (((size_t)b * NC + c) * NM + m0 + mlocal) * 2) =
            make_float2(vr, vi);
    }
}

extern "C" void kernel_launch(void* const* d_in, const int* in_sizes, int n_in,
                              void* d_out, int out_size)
{
    const float* xre  = (const float*)d_in[0];   // [B,C,H,W] f32
    const float* xim  = (const float*)d_in[1];   // [B,C,H,W] f32
    const float* traj = (const float*)d_in[2];   // [B,M,2]   f32
    float* out        = (float*)d_out;           // [B,C,M,2] f32

    cudaFuncSetAttribute(nufft2_mma_kernel,
                         cudaFuncAttributeMaxDynamicSharedMemorySize, SMEM_TOTAL);
    nufft2_mma_kernel<<<NBATCH * MTILES, NTHREADS, SMEM_TOTAL>>>(xre, xim, traj, out);
}

// round 9
// speedup vs baseline: 1.7614x; 1.0034x over previous
#include <cuda_runtime.h>
#include <cstdint>

// Type-2 NUFFT, separable:
//   stage 1 (tensor, mma.sync tf32): S[m, n=(iy*4+c)] = sum_ix E[m,ix] * X[n,ix]
//   stage 2 (FFMA, in-register):     y[b,c,m] = sum_iy ey[m,iy] (*) S[m,iy,c]
// One CTA per (frame, 64-sample tile): 16*32 = 512 CTAs, 512 threads (16 warps).
// Warp = (mb = wid&3) m16-block x (qt = wid>>2) 64-col n-quarter; 256 MMA/warp.
// Dr = Er*Xr + (-Ei)*Xi ; Di = Er*Xi + Ei*Xr   (-Ei formed by in-register XOR)

#define NBATCH 16
#define NC 4
#define NH 64
#define NW 64
#define NM 2048

#define MT 64                    // samples per CTA
#define MTILES (NM / MT)         // 32
#define NGEMM 256                // n = iy*4 + c
#define KDIM 64                  // k = ix
#define NTHREADS 512

#define ESTRIDE 68               // floats per E row
#define XSTRIDE 264              // floats per X k-row

#define OFF_ER   0
#define OFF_EI   (OFF_ER  + MT * ESTRIDE * 4)          // 17408
#define OFF_XR   (OFF_EI  + MT * ESTRIDE * 4)          // 34816
#define OFF_XI   (OFF_XR  + KDIM * XSTRIDE * 4)        // 102400
#define OFF_PART (OFF_XI  + KDIM * XSTRIDE * 4)        // 169984
#define SMEM_TOTAL (OFF_PART + 4 * MT * NC * 2 * 4)    // 178176 B

static __device__ __forceinline__ uint32_t f2tf32(float f) {
    uint32_t u;
    asm("cvt.rna.tf32.f32 %0, %1;" : "=r"(u) : "f"(f));
    return u;
}

static __device__ __forceinline__ float2 twiddle(float t, int i) {
    float ph = -t * (float)(i - 32);
    ph -= 6.283185307179586f * rintf(ph * 0.15915494309189535f);
    float s, c;
    __sincosf(ph, &s, &c);
    return make_float2(c, s);
}

static __device__ __forceinline__ void mma8(float* d, const uint32_t* a, const uint32_t* b) {
    asm volatile(
        "mma.sync.aligned.m16n8k8.row.col.f32.tf32.tf32.f32 "
        "{%0,%1,%2,%3}, {%4,%5,%6,%7}, {%8,%9}, {%0,%1,%2,%3};"
        : "+f"(d[0]), "+f"(d[1]), "+f"(d[2]), "+f"(d[3])
        : "r"(a[0]), "r"(a[1]), "r"(a[2]), "r"(a[3]), "r"(b[0]), "r"(b[1]));
}

__global__ void __launch_bounds__(NTHREADS, 1)
nufft2_mma_kernel(const float* __restrict__ xre, const float* __restrict__ xim,
                  const float* __restrict__ traj, float* __restrict__ out)
{
    extern __shared__ char smc[];
    uint32_t* ER  = (uint32_t*)(smc + OFF_ER);
    uint32_t* EI  = (uint32_t*)(smc + OFF_EI);
    uint32_t* XR  = (uint32_t*)(smc + OFF_XR);
    uint32_t* XI  = (uint32_t*)(smc + OFF_XI);
    float*    PART = (float*)(smc + OFF_PART);   // [qt=4][m=64][c=4][re/im]

    const int b     = blockIdx.x >> 5;
    const int mtile = blockIdx.x & 31;
    const int m0    = mtile * MT;
    const int tid   = threadIdx.x;
    const int wid   = tid >> 5;
    const int lane  = tid & 31;

    // ---- stage E: Er/Ei[m][k], tf32; ph = -traj[...,1]*(k-32) ----
    #pragma unroll 2
    for (int e = tid; e < MT * KDIM; e += NTHREADS) {
        int ml = e >> 6, k = e & 63;
        float t1 = __ldg(traj + ((size_t)b * NM + m0 + ml) * 2 + 1);
        float2 w = twiddle(t1, k);
        int d = ml * ESTRIDE + k;
        ER[d] = f2tf32(w.x);
        EI[d] = f2tf32(w.y);
    }

    // ---- stage X: Xr/Xi[k][n], n = iy*4+c, tf32 (STS conflict-free: n fastest) ----
    const float* xrb = xre + (size_t)b * (NC * NH * NW);
    const float* xib = xim + (size_t)b * (NC * NH * NW);
    #pragma unroll 4
    for (int idx = tid; idx < KDIM * NGEMM; idx += NTHREADS) {
        int n = idx & 255, k = idx >> 8;
        int g = (n & 3) * 4096 + (n >> 2) * 64 + k;
        int d = k * XSTRIDE + n;
        XR[d] = f2tf32(__ldg(xrb + g));
        XI[d] = f2tf32(__ldg(xib + g));
    }
    __syncthreads();

    // ---- mainloop: warp = m16-block mb x n-quarter qt ----
    const int mb = wid & 3;
    const int qt = wid >> 2;
    const int g  = lane >> 2;        // groupID
    const int q  = lane & 3;         // threadID-in-group
    const int r0 = (mb * 16 + g) * ESTRIDE;
    const int r1 = r0 + 8 * ESTRIDE;

    float dr[8][4], di[8][4];
    #pragma unroll
    for (int nb = 0; nb < 8; ++nb)
        #pragma unroll
        for (int r = 0; r < 4; ++r) { dr[nb][r] = 0.f; di[nb][r] = 0.f; }

    uint32_t aR[4], aI[4];
    {
        const int k0 = q;
        aR[0] = ER[r0 + k0]; aR[1] = ER[r1 + k0];
        aR[2] = ER[r0 + k0 + 4]; aR[3] = ER[r1 + k0 + 4];
        aI[0] = EI[r0 + k0]; aI[1] = EI[r1 + k0];
        aI[2] = EI[r0 + k0 + 4]; aI[3] = EI[r1 + k0 + 4];
    }

    #pragma unroll 1
    for (int ks = 0; ks < 8; ++ks) {
        const int k0 = ks * 8 + q;
        uint32_t aN[4];
        #pragma unroll
        for (int r = 0; r < 4; ++r) aN[r] = aI[r] ^ 0x80000000u;

        uint32_t aRn[4], aIn[4];
        if (ks < 7) {
            const int kn = k0 + 8;
            aRn[0] = ER[r0 + kn]; aRn[1] = ER[r1 + kn];
            aRn[2] = ER[r0 + kn + 4]; aRn[3] = ER[r1 + kn + 4];
            aIn[0] = EI[r0 + kn]; aIn[1] = EI[r1 + kn];
            aIn[2] = EI[r0 + kn + 4]; aIn[3] = EI[r1 + kn + 4];
        }

        #pragma unroll
        for (int nb = 0; nb < 8; ++nb) {
            int ncol = qt * 64 + nb * 8 + g;
            uint32_t bR[2], bI[2];
            bR[0] = XR[k0 * XSTRIDE + ncol];
            bR[1] = XR[(k0 + 4) * XSTRIDE + ncol];
            bI[0] = XI[k0 * XSTRIDE + ncol];
            bI[1] = XI[(k0 + 4) * XSTRIDE + ncol];
            mma8(dr[nb], aR, bR);
            mma8(dr[nb], aN, bI);
            mma8(di[nb], aR, bI);
            mma8(di[nb], aI, bR);
        }

        #pragma unroll
        for (int r = 0; r < 4; ++r) { aR[r] = aRn[r]; aI[r] = aIn[r]; }
    }

    // ---- epilogue: ey twiddle in-register, reduce iy ----
    // d-frag: rows {g, g+8} (regs {0,1},{2,3}), cols n = qt*64+nb*8+2q+{0,1}
    //   -> iy = qt*16 + nb*2 + (q>>1), c = (q&1)*2 + {0,1}
    const int cb = (q & 1) * 2;
    #pragma unroll
    for (int rr = 0; rr < 2; ++rr) {
        int rowl = mb * 16 + g + rr * 8;
        float t0 = __ldg(traj + ((size_t)b * NM + m0 + rowl) * 2 + 0);
        float aR0 = 0.f, aI0 = 0.f, aR1 = 0.f, aI1 = 0.f;
        #pragma unroll
        for (int nb = 0; nb < 8; ++nb) {
            float2 ey = twiddle(t0, qt * 16 + nb * 2 + (q >> 1));
            float sr0 = dr[nb][rr * 2 + 0], si0 = di[nb][rr * 2 + 0];
            float sr1 = dr[nb][rr * 2 + 1], si1 = di[nb][rr * 2 + 1];
            aR0 = fmaf(ey.x, sr0, fmaf(-ey.y, si0, aR0));
            aI0 = fmaf(ey.x, si0, fmaf( ey.y, sr0, aI0));
            aR1 = fmaf(ey.x, sr1, fmaf(-ey.y, si1, aR1));
            aI1 = fmaf(ey.x, si1, fmaf( ey.y, sr1, aI1));
        }
        // partner lane (q ^ 2) holds the other iy parity, same c pair
        aR0 += __shfl_xor_sync(0xffffffffu, aR0, 2);
        aI0 += __shfl_xor_sync(0xffffffffu, aI0, 2);
        aR1 += __shfl_xor_sync(0xffffffffu, aR1, 2);
        aI1 += __shfl_xor_sync(0xffffffffu, aI1, 2);
        if (q < 2) {
            float* p = PART + ((qt * MT + rowl) * NC + cb) * 2;
            p[0] = aR0; p[1] = aI0; p[2] = aR1; p[3] = aI1;
        }
    }
    __syncthreads();

    // ---- combine 4 n-quarters, write out ----
    if (tid < MT * NC) {
        int mlocal = tid >> 2, c = tid & 3;
        float vr = 0.f, vi = 0.f;
        #pragma unroll
        for (int qq = 0; qq < 4; ++qq) {
            const float* p = PART + ((qq * MT + mlocal) * NC + c) * 2;
            vr += p[0]; vi += p[1];
        }
        *(float2*)(out + (((size_t)b * NC + c) * NM + m0 + mlocal) * 2) =
            make_float2(vr, vi);
    }
}

extern "C" void kernel_launch(void* const* d_in, const int* in_sizes, int n_in,
                              void* d_out, int out_size)
{
    const float* xre  = (const float*)d_in[0];   // [B,C,H,W] f32
    const float* xim  = (const float*)d_in[1];   // [B,C,H,W] f32
    const float* traj = (const float*)d_in[2];   // [B,M,2]   f32
    float* out        = (float*)d_out;           // [B,C,M,2] f32

    cudaFuncSetAttribute(nufft2_mma_kernel,
                         cudaFuncAttributeMaxDynamicSharedMemorySize, SMEM_TOTAL);
    nufft2_mma_kernel<<<NBATCH * MTILES, NTHREADS, SMEM_TOTAL>>>(xre, xim, traj, out);
}

// round 10
// speedup vs baseline: 4.5577x; 2.5876x over previous
#include <cuda_runtime.h>
#include <cstdint>

// Type-2 NUFFT, separable:
//   stage 1 (tensor, mma.sync tf32): S[m, n=(iy*4+c)] = sum_ix E[m,ix] * X[n,ix]
//   stage 2 (FFMA, in-register):     y[b,c,m] = sum_iy ey[m,iy] (*) S[m,iy,c]
// One CTA per (frame, 64-sample tile): 512 CTAs, 512 threads (16 warps).
// X stored n-major [n][k] so gmem staging is float4-coalesced AND the
// B-fragment LDS pattern (banks 4g+q) is conflict-free.
// Dr = Er*Xr + (-Ei)*Xi ; Di = Er*Xi + Ei*Xr   (-Ei via in-register XOR)

#define NBATCH 16
#define NC 4
#define NH 64
#define NW 64
#define NM 2048

#define MT 64                    // samples per CTA
#define MTILES (NM / MT)         // 32
#define NGEMM 256                // n = iy*4 + c
#define KDIM 64                  // k = ix
#define NTHREADS 512

#define ESTRIDE 68               // floats per E row (m-major)
#define XSTRIDE 68               // floats per X row (n-major)

#define OFF_ER   0
#define OFF_EI   (OFF_ER  + MT * ESTRIDE * 4)          // 17408
#define OFF_XR   (OFF_EI  + MT * ESTRIDE * 4)          // 34816
#define OFF_XI   (OFF_XR  + NGEMM * XSTRIDE * 4)       // 104448
#define OFF_PART (OFF_XI  + NGEMM * XSTRIDE * 4)       // 174080
#define SMEM_TOTAL (OFF_PART + 4 * MT * NC * 2 * 4)    // 182272 B

static __device__ __forceinline__ uint32_t f2tf32(float f) {
    uint32_t u;
    asm("cvt.rna.tf32.f32 %0, %1;" : "=r"(u) : "f"(f));
    return u;
}

static __device__ __forceinline__ float2 twiddle(float t, int i) {
    float ph = -t * (float)(i - 32);
    ph -= 6.283185307179586f * rintf(ph * 0.15915494309189535f);
    float s, c;
    __sincosf(ph, &s, &c);
    return make_float2(c, s);
}

static __device__ __forceinline__ void mma8(float* d, const uint32_t* a, const uint32_t* b) {
    asm volatile(
        "mma.sync.aligned.m16n8k8.row.col.f32.tf32.tf32.f32 "
        "{%0,%1,%2,%3}, {%4,%5,%6,%7}, {%8,%9}, {%0,%1,%2,%3};"
        : "+f"(d[0]), "+f"(d[1]), "+f"(d[2]), "+f"(d[3])
        : "r"(a[0]), "r"(a[1]), "r"(a[2]), "r"(a[3]), "r"(b[0]), "r"(b[1]));
}

__global__ void __launch_bounds__(NTHREADS, 1)
nufft2_mma_kernel(const float* __restrict__ xre, const float* __restrict__ xim,
                  const float* __restrict__ traj, float* __restrict__ out)
{
    extern __shared__ char smc[];
    uint32_t* ER  = (uint32_t*)(smc + OFF_ER);
    uint32_t* EI  = (uint32_t*)(smc + OFF_EI);
    uint32_t* XR  = (uint32_t*)(smc + OFF_XR);
    uint32_t* XI  = (uint32_t*)(smc + OFF_XI);
    float*    PART = (float*)(smc + OFF_PART);   // [qt=4][m=64][c=4][re/im]

    const int b     = blockIdx.x >> 5;
    const int mtile = blockIdx.x & 31;
    const int m0    = mtile * MT;
    const int tid   = threadIdx.x;
    const int wid   = tid >> 5;
    const int lane  = tid & 31;

    // ---- stage E: Er/Ei[m][k], tf32; ph = -traj[...,1]*(k-32) ----
    #pragma unroll 2
    for (int e = tid; e < MT * KDIM; e += NTHREADS) {
        int ml = e >> 6, k = e & 63;
        float t1 = __ldg(traj + ((size_t)b * NM + m0 + ml) * 2 + 1);
        float2 w = twiddle(t1, k);
        int d = ml * ESTRIDE + k;
        ER[d] = f2tf32(w.x);
        EI[d] = f2tf32(w.y);
    }

    // ---- stage X: Xr/Xi[n = iy*4+c][k], float4-coalesced LDG + STS.128 ----
    const float4* xr4 = (const float4*)(xre + (size_t)b * (NC * NH * NW));
    const float4* xi4 = (const float4*)(xim + (size_t)b * (NC * NH * NW));
    #pragma unroll
    for (int f = tid; f < (NC * NH * NW) / 4; f += NTHREADS) {   // 8 iters
        int kq = f & 15;             // float4 within row (k = 4*kq..4*kq+3)
        int iy = (f >> 4) & 63;
        int c  = f >> 10;
        int n  = iy * 4 + c;
        float4 vr = __ldg(xr4 + f);
        float4 vi = __ldg(xi4 + f);
        uint4 wr = make_uint4(f2tf32(vr.x), f2tf32(vr.y), f2tf32(vr.z), f2tf32(vr.w));
        uint4 wi = make_uint4(f2tf32(vi.x), f2tf32(vi.y), f2tf32(vi.z), f2tf32(vi.w));
        *(uint4*)(XR + n * XSTRIDE + kq * 4) = wr;
        *(uint4*)(XI + n * XSTRIDE + kq * 4) = wi;
    }
    __syncthreads();

    // ---- mainloop: warp = m16-block (mb = wid&3) x 64-col n-quarter (qt = wid>>2) ----
    const int mb = wid & 3;
    const int qt = wid >> 2;
    const int g  = lane >> 2;        // groupID
    const int q  = lane & 3;         // threadID-in-group
    const int r0 = (mb * 16 + g) * ESTRIDE;
    const int r1 = r0 + 8 * ESTRIDE;

    float dr[8][4], di[8][4];
    #pragma unroll
    for (int nb = 0; nb < 8; ++nb)
        #pragma unroll
        for (int r = 0; r < 4; ++r) { dr[nb][r] = 0.f; di[nb][r] = 0.f; }

    uint32_t aR[4], aI[4];
    {
        const int k0 = q;
        aR[0] = ER[r0 + k0]; aR[1] = ER[r1 + k0];
        aR[2] = ER[r0 + k0 + 4]; aR[3] = ER[r1 + k0 + 4];
        aI[0] = EI[r0 + k0]; aI[1] = EI[r1 + k0];
        aI[2] = EI[r0 + k0 + 4]; aI[3] = EI[r1 + k0 + 4];
    }

    #pragma unroll 1
    for (int ks = 0; ks < 8; ++ks) {
        const int k0 = ks * 8 + q;
        uint32_t aN[4];
        #pragma unroll
        for (int r = 0; r < 4; ++r) aN[r] = aI[r] ^ 0x80000000u;

        uint32_t aRn[4], aIn[4];
        if (ks < 7) {
            const int kn = k0 + 8;
            aRn[0] = ER[r0 + kn]; aRn[1] = ER[r1 + kn];
            aRn[2] = ER[r0 + kn + 4]; aRn[3] = ER[r1 + kn + 4];
            aIn[0] = EI[r0 + kn]; aIn[1] = EI[r1 + kn];
            aIn[2] = EI[r0 + kn + 4]; aIn[3] = EI[r1 + kn + 4];
        }

        #pragma unroll
        for (int nb = 0; nb < 8; ++nb) {
            int nrow = (qt * 64 + nb * 8 + g) * XSTRIDE;   // n-major X
            uint32_t bR[2], bI[2];
            bR[0] = XR[nrow + k0];
            bR[1] = XR[nrow + k0 + 4];
            bI[0] = XI[nrow + k0];
            bI[1] = XI[nrow + k0 + 4];
            mma8(dr[nb], aR, bR);
            mma8(dr[nb], aN, bI);
            mma8(di[nb], aR, bI);
            mma8(di[nb], aI, bR);
        }

        #pragma unroll
        for (int r = 0; r < 4; ++r) { aR[r] = aRn[r]; aI[r] = aIn[r]; }
    }

    // ---- epilogue: ey twiddle in-register, reduce iy ----
    // d-frag: rows {g, g+8} (regs {0,1},{2,3}), cols n = qt*64+nb*8+2q+{0,1}
    //   -> iy = qt*16 + nb*2 + (q>>1), c = (q&1)*2 + {0,1}
    const int cb = (q & 1) * 2;
    #pragma unroll
    for (int rr = 0; rr < 2; ++rr) {
        int rowl = mb * 16 + g + rr * 8;
        float t0 = __ldg(traj + ((size_t)b * NM + m0 + rowl) * 2 + 0);
        float aR0 = 0.f, aI0 = 0.f, aR1 = 0.f, aI1 = 0.f;
        #pragma unroll
        for (int nb = 0; nb < 8; ++nb) {
            float2 ey = twiddle(t0, qt * 16 + nb * 2 + (q >> 1));
            float sr0 = dr[nb][rr * 2 + 0], si0 = di[nb][rr * 2 + 0];
            float sr1 = dr[nb][rr * 2 + 1], si1 = di[nb][rr * 2 + 1];
            aR0 = fmaf(ey.x, sr0, fmaf(-ey.y, si0, aR0));
            aI0 = fmaf(ey.x, si0, fmaf( ey.y, sr0, aI0));
            aR1 = fmaf(ey.x, sr1, fmaf(-ey.y, si1, aR1));
            aI1 = fmaf(ey.x, si1, fmaf( ey.y, sr1, aI1));
        }
        // partner lane (q ^ 2) holds the other iy parity, same c pair
        aR0 += __shfl_xor_sync(0xffffffffu, aR0, 2);
        aI0 += __shfl_xor_sync(0xffffffffu, aI0, 2);
        aR1 += __shfl_xor_sync(0xffffffffu, aR1, 2);
        aI1 += __shfl_xor_sync(0xffffffffu, aI1, 2);
        if (q < 2) {
            float* p = PART + ((qt * MT + rowl) * NC + cb) * 2;
            p[0] = aR0; p[1] = aI0; p[2] = aR1; p[3] = aI1;
        }
    }
    __syncthreads();

    // ---- combine 4 n-quarters, write out ----
    if (tid < MT * NC) {
        int mlocal = tid >> 2, c = tid & 3;
        float vr = 0.f, vi = 0.f;
        #pragma unroll
        for (int qq = 0; qq < 4; ++qq) {
            const float* p = PART + ((qq * MT + mlocal) * NC + c) * 2;
            vr += p[0]; vi += p[1];
        }
        *(float2*)(out + (((size_t)b * NC + c) * NM + m0 + mlocal) * 2) =
            make_float2(vr, vi);
    }
}

extern "C" void kernel_launch(void* const* d_in, const int* in_sizes, int n_in,
                              void* d_out, int out_size)
{
    const float* xre  = (const float*)d_in[0];   // [B,C,H,W] f32
    const float* xim  = (const float*)d_in[1];   // [B,C,H,W] f32
    const float* traj = (const float*)d_in[2];   // [B,M,2]   f32
    float* out        = (float*)d_out;           // [B,C,M,2] f32

    cudaFuncSetAttribute(nufft2_mma_kernel,
                         cudaFuncAttributeMaxDynamicSharedMemorySize, SMEM_TOTAL);
    nufft2_mma_kernel<<<NBATCH * MTILES, NTHREADS, SMEM_TOTAL>>>(xre, xim, traj, out);
}

// round 11
// speedup vs baseline: 4.5836x; 1.0057x over previous
#include <cuda_runtime.h>
#include <cstdint>

// Type-2 NUFFT, separable:
//   stage 1 (tensor, mma.sync tf32): S[m, n=(iy*4+c)] = sum_ix E[m,ix] * X[n,ix]
//   stage 2 (FFMA, in-register):     y[b,c,m] = sum_iy ey[m,iy] (*) S[m,iy,c]
// One CTA per (frame, 64-sample tile): 512 CTAs, 512 threads (16 warps).
// X stored n-major [n][k] so gmem staging is float4-coalesced AND the
// B-fragment LDS pattern (banks 4g+q) is conflict-free.
// Dr = Er*Xr + (-Ei)*Xi ; Di = Er*Xi + Ei*Xr   (-Ei via in-register XOR)

#define NBATCH 16
#define NC 4
#define NH 64
#define NW 64
#define NM 2048

#define MT 64                    // samples per CTA
#define MTILES (NM / MT)         // 32
#define NGEMM 256                // n = iy*4 + c
#define KDIM 64                  // k = ix
#define NTHREADS 512

#define ESTRIDE 68               // floats per E row (m-major)
#define XSTRIDE 68               // floats per X row (n-major)

#define OFF_ER   0
#define OFF_EI   (OFF_ER  + MT * ESTRIDE * 4)          // 17408
#define OFF_XR   (OFF_EI  + MT * ESTRIDE * 4)          // 34816
#define OFF_XI   (OFF_XR  + NGEMM * XSTRIDE * 4)       // 104448
#define OFF_PART (OFF_XI  + NGEMM * XSTRIDE * 4)       // 174080
#define SMEM_TOTAL (OFF_PART + 4 * MT * NC * 2 * 4)    // 182272 B

static __device__ __forceinline__ uint32_t f2tf32(float f) {
    uint32_t u;
    asm("cvt.rna.tf32.f32 %0, %1;" : "=r"(u) : "f"(f));
    return u;
}

static __device__ __forceinline__ float2 twiddle(float t, int i) {
    float ph = -t * (float)(i - 32);
    ph -= 6.283185307179586f * rintf(ph * 0.15915494309189535f);
    float s, c;
    __sincosf(ph, &s, &c);
    return make_float2(c, s);
}

static __device__ __forceinline__ void mma8(float* d, const uint32_t* a, const uint32_t* b) {
    asm volatile(
        "mma.sync.aligned.m16n8k8.row.col.f32.tf32.tf32.f32 "
        "{%0,%1,%2,%3}, {%4,%5,%6,%7}, {%8,%9}, {%0,%1,%2,%3};"
        : "+f"(d[0]), "+f"(d[1]), "+f"(d[2]), "+f"(d[3])
        : "r"(a[0]), "r"(a[1]), "r"(a[2]), "r"(a[3]), "r"(b[0]), "r"(b[1]));
}

__global__ void __launch_bounds__(NTHREADS, 1)
nufft2_mma_kernel(const float* __restrict__ xre, const float* __restrict__ xim,
                  const float* __restrict__ traj, float* __restrict__ out)
{
    extern __shared__ char smc[];
    uint32_t* ER  = (uint32_t*)(smc + OFF_ER);
    uint32_t* EI  = (uint32_t*)(smc + OFF_EI);
    uint32_t* XR  = (uint32_t*)(smc + OFF_XR);
    uint32_t* XI  = (uint32_t*)(smc + OFF_XI);
    float*    PART = (float*)(smc + OFF_PART);   // [qt=4][m=64][c=4][re/im]

    const int b     = blockIdx.x >> 5;
    const int mtile = blockIdx.x & 31;
    const int m0    = mtile * MT;
    const int tid   = threadIdx.x;
    const int wid   = tid >> 5;
    const int lane  = tid & 31;

    // ---- stage E: Er/Ei[m][k], tf32; ph = -traj[...,1]*(k-32) ----
    #pragma unroll 2
    for (int e = tid; e < MT * KDIM; e += NTHREADS) {
        int ml = e >> 6, k = e & 63;
        float t1 = __ldg(traj + ((size_t)b * NM + m0 + ml) * 2 + 1);
        float2 w = twiddle(t1, k);
        int d = ml * ESTRIDE + k;
        ER[d] = f2tf32(w.x);
        EI[d] = f2tf32(w.y);
    }

    // ---- stage X: Xr/Xi[n = iy*4+c][k], float4-coalesced LDG + STS.128 ----
    const float4* xr4 = (const float4*)(xre + (size_t)b * (NC * NH * NW));
    const float4* xi4 = (const float4*)(xim + (size_t)b * (NC * NH * NW));
    #pragma unroll
    for (int f = tid; f < (NC * NH * NW) / 4; f += NTHREADS) {   // 8 iters
        int kq = f & 15;             // float4 within row (k = 4*kq..4*kq+3)
        int iy = (f >> 4) & 63;
        int c  = f >> 10;
        int n  = iy * 4 + c;
        float4 vr = __ldg(xr4 + f);
        float4 vi = __ldg(xi4 + f);
        uint4 wr = make_uint4(f2tf32(vr.x), f2tf32(vr.y), f2tf32(vr.z), f2tf32(vr.w));
        uint4 wi = make_uint4(f2tf32(vi.x), f2tf32(vi.y), f2tf32(vi.z), f2tf32(vi.w));
        *(uint4*)(XR + n * XSTRIDE + kq * 4) = wr;
        *(uint4*)(XI + n * XSTRIDE + kq * 4) = wi;
    }
    __syncthreads();

    // ---- mainloop: warp = m16-block (mb = wid&3) x 64-col n-quarter (qt = wid>>2) ----
    const int mb = wid & 3;
    const int qt = wid >> 2;
    const int g  = lane >> 2;        // groupID
    const int q  = lane & 3;         // threadID-in-group
    const int r0 = (mb * 16 + g) * ESTRIDE;
    const int r1 = r0 + 8 * ESTRIDE;

    float dr[8][4], di[8][4];
    #pragma unroll
    for (int nb = 0; nb < 8; ++nb)
        #pragma unroll
        for (int r = 0; r < 4; ++r) { dr[nb][r] = 0.f; di[nb][r] = 0.f; }

    uint32_t aR[4], aI[4];
    {
        const int k0 = q;
        aR[0] = ER[r0 + k0]; aR[1] = ER[r1 + k0];
        aR[2] = ER[r0 + k0 + 4]; aR[3] = ER[r1 + k0 + 4];
        aI[0] = EI[r0 + k0]; aI[1] = EI[r1 + k0];
        aI[2] = EI[r0 + k0 + 4]; aI[3] = EI[r1 + k0 + 4];
    }

    #pragma unroll 1
    for (int ks = 0; ks < 8; ++ks) {
        const int k0 = ks * 8 + q;
        uint32_t aN[4];
        #pragma unroll
        for (int r = 0; r < 4; ++r) aN[r] = aI[r] ^ 0x80000000u;

        uint32_t aRn[4], aIn[4];
        if (ks < 7) {
            const int kn = k0 + 8;
            aRn[0] = ER[r0 + kn]; aRn[1] = ER[r1 + kn];
            aRn[2] = ER[r0 + kn + 4]; aRn[3] = ER[r1 + kn + 4];
            aIn[0] = EI[r0 + kn]; aIn[1] = EI[r1 + kn];
            aIn[2] = EI[r0 + kn + 4]; aIn[3] = EI[r1 + kn + 4];
        }

        #pragma unroll
        for (int nb = 0; nb < 8; ++nb) {
            int nrow = (qt * 64 + nb * 8 + g) * XSTRIDE;   // n-major X
            uint32_t bR[2], bI[2];
            bR[0] = XR[nrow + k0];
            bR[1] = XR[nrow + k0 + 4];
            bI[0] = XI[nrow + k0];
            bI[1] = XI[nrow + k0 + 4];
            mma8(dr[nb], aR, bR);
            mma8(dr[nb], aN, bI);
            mma8(di[nb], aR, bI);
            mma8(di[nb], aI, bR);
        }

        #pragma unroll
        for (int r = 0; r < 4; ++r) { aR[r] = aRn[r]; aI[r] = aIn[r]; }
    }

    // ---- epilogue: ey twiddle in-register, reduce iy ----
    // d-frag: rows {g, g+8} (regs {0,1},{2,3}), cols n = qt*64+nb*8+2q+{0,1}
    //   -> iy = qt*16 + nb*2 + (q>>1), c = (q&1)*2 + {0,1}
    const int cb = (q & 1) * 2;
    #pragma unroll
    for (int rr = 0; rr < 2; ++rr) {
        int rowl = mb * 16 + g + rr * 8;
        float t0 = __ldg(traj + ((size_t)b * NM + m0 + rowl) * 2 + 0);
        float aR0 = 0.f, aI0 = 0.f, aR1 = 0.f, aI1 = 0.f;
        #pragma unroll
        for (int nb = 0; nb < 8; ++nb) {
            float2 ey = twiddle(t0, qt * 16 + nb * 2 + (q >> 1));
            float sr0 = dr[nb][rr * 2 + 0], si0 = di[nb][rr * 2 + 0];
            float sr1 = dr[nb][rr * 2 + 1], si1 = di[nb][rr * 2 + 1];
            aR0 = fmaf(ey.x, sr0, fmaf(-ey.y, si0, aR0));
            aI0 = fmaf(ey.x, si0, fmaf( ey.y, sr0, aI0));
            aR1 = fmaf(ey.x, sr1, fmaf(-ey.y, si1, aR1));
            aI1 = fmaf(ey.x, si1, fmaf( ey.y, sr1, aI1));
        }
        // partner lane (q ^ 2) holds the other iy parity, same c pair
        aR0 += __shfl_xor_sync(0xffffffffu, aR0, 2);
        aI0 += __shfl_xor_sync(0xffffffffu, aI0, 2);
        aR1 += __shfl_xor_sync(0xffffffffu, aR1, 2);
        aI1 += __shfl_xor_sync(0xffffffffu, aI1, 2);
        if (q < 2) {
            float* p = PART + ((qt * MT + rowl) * NC + cb) * 2;
            p[0] = aR0; p[1] = aI0; p[2] = aR1; p[3] = aI1;
        }
    }
    __syncthreads();

    // ---- combine 4 n-quarters, write out ----
    if (tid < MT * NC) {
        int mlocal = tid >> 2, c = tid & 3;
        float vr = 0.f, vi = 0.f;
        #pragma unroll
        for (int qq = 0; qq < 4; ++qq) {
            const float* p = PART + ((qq * MT + mlocal) * NC + c) * 2;
            vr += p[0]; vi += p[1];
        }
        *(float2*)(out + (((size_t)b * NC + c) * NM + m0 + mlocal) * 2) =
            make_float2(vr, vi);
    }
}

extern "C" void kernel_launch(void* const* d_in, const int* in_sizes, int n_in,
                              void* d_out, int out_size)
{
    const float* xre  = (const float*)d_in[0];   // [B,C,H,W] f32
    const float* xim  = (const float*)d_in[1];   // [B,C,H,W] f32
    const float* traj = (const float*)d_in[2];   // [B,M,2]   f32
    float* out        = (float*)d_out;           // [B,C,M,2] f32

    cudaFuncSetAttribute(nufft2_mma_kernel,
                         cudaFuncAttributeMaxDynamicSharedMemorySize, SMEM_TOTAL);
    nufft2_mma_kernel<<<NBATCH * MTILES, NTHREADS, SMEM_TOTAL>>>(xre, xim, traj, out);
}